// round 13
// baseline (speedup 1.0000x reference)
#include <cuda_runtime.h>
#include <cuda_bf16.h>
#include <cstdint>
#include <cstddef>

// ============================================================================
// HQQSVDLinear forward_int8 on GB300 (sm_103 base ISA; tcgen05 blocked by
// toolchain — R6). R7 pure mma.sync 926us (pipe-saturated ~260 MACs/cyc/SM).
// R8 hybrid mma+dp4a 742us (latency-bound, 2 warps/SMSP, issue 45%).
// R10 crossbar-bound; R11 occupancy-bound; R12 2-CTA w/ forced 128 regs ->
// mainloop SPILLS (L2 37.6%) -> 854us.
// R13: 2 CTAs/SM with genuine <=128-reg mainloop: per-mi a-buffer in tensor
// path, per-j b-buffer in dp4a path, no cached epilogue arrays. Cross-CTA
// warp pairs per SMSP hide LDS/ldsm latency.
// Both paths accumulate exact int32 vs the reference GEMM.
// ============================================================================

#define NTOK 4096
#define ODIM 4096
#define IDIM 4096

__device__ int8_t g_Xq[(size_t)NTOK * IDIM];          // 16 MB
__device__ int8_t g_Wq[(size_t)ODIM * IDIM];          // 16 MB
__device__ float  g_corr[(size_t)ODIM * IDIM];        // 64 MB
__device__ float  g_sx[NTOK];
__device__ float  g_sw[ODIM];

// ---------------------------------------------------------------------------
__device__ __forceinline__ uint32_t smem_u32(const void* p) {
    uint32_t a;
    asm("{ .reg .u64 t; cvta.to.shared.u64 t, %1; cvt.u32.u64 %0, t; }"
        : "=r"(a) : "l"(p));
    return a;
}

__device__ __forceinline__ void cp_async16(uint32_t dst, const void* src) {
    asm volatile("cp.async.cg.shared.global [%0], [%1], 16;"
                 :: "r"(dst), "l"(src) : "memory");
}

__device__ __forceinline__ void ldsm4(uint32_t* r, uint32_t addr) {
    asm volatile("ldmatrix.sync.aligned.m8n8.x4.shared.b16 {%0,%1,%2,%3}, [%4];"
                 : "=r"(r[0]), "=r"(r[1]), "=r"(r[2]), "=r"(r[3]) : "r"(addr));
}

__device__ __forceinline__ void lds128(uint32_t* r, uint32_t addr) {
    asm volatile("ld.shared.v4.b32 {%0,%1,%2,%3}, [%4];"
                 : "=r"(r[0]), "=r"(r[1]), "=r"(r[2]), "=r"(r[3]) : "r"(addr));
}

__device__ __forceinline__ void mma_s8(int* c, const uint32_t* a, const uint32_t* b) {
    asm volatile(
        "mma.sync.aligned.m16n8k32.row.col.s32.s8.s8.s32 "
        "{%0,%1,%2,%3}, {%4,%5,%6,%7}, {%8,%9}, {%0,%1,%2,%3};"
        : "+r"(c[0]), "+r"(c[1]), "+r"(c[2]), "+r"(c[3])
        : "r"(a[0]), "r"(a[1]), "r"(a[2]), "r"(a[3]), "r"(b[0]), "r"(b[1]));
}

// ---------------------------------------------------------------------------
// Kernel 1: per-token activation quant.  x[n,:] -> g_Xq (int8), g_sx[n]
// ---------------------------------------------------------------------------
__global__ void __launch_bounds__(256) k_quant_x(const float* __restrict__ x) {
    const int n = blockIdx.x, t = threadIdx.x;
    const float4* xr = (const float4*)(x + (size_t)n * IDIM) + t * 4;
    float v[16];
    float4 a0 = xr[0], a1 = xr[1], a2 = xr[2], a3 = xr[3];
    v[0]=a0.x; v[1]=a0.y; v[2]=a0.z; v[3]=a0.w;
    v[4]=a1.x; v[5]=a1.y; v[6]=a1.z; v[7]=a1.w;
    v[8]=a2.x; v[9]=a2.y; v[10]=a2.z; v[11]=a2.w;
    v[12]=a3.x; v[13]=a3.y; v[14]=a3.z; v[15]=a3.w;

    float m = 0.f;
    #pragma unroll
    for (int k = 0; k < 16; k++) m = fmaxf(m, fabsf(v[k]));

    __shared__ float red[8];
    __shared__ float s_inv;
    #pragma unroll
    for (int off = 16; off; off >>= 1) m = fmaxf(m, __shfl_xor_sync(0xFFFFFFFFu, m, off));
    if ((t & 31) == 0) red[t >> 5] = m;
    __syncthreads();
    if (t == 0) {
        float mm = red[0];
        #pragma unroll
        for (int k = 1; k < 8; k++) mm = fmaxf(mm, red[k]);
        float sv = mm / 127.0f;
        g_sx[n] = sv;
        s_inv = 1.0f / sv;
    }
    __syncthreads();
    float inv = s_inv;

    alignas(16) int8_t q[16];
    #pragma unroll
    for (int k = 0; k < 16; k++) {
        float r = rintf(v[k] * inv);
        r = fminf(fmaxf(r, -128.f), 127.f);
        q[k] = (int8_t)(int)r;
    }
    *(int4*)(g_Xq + (size_t)n * IDIM + t * 16) = *(const int4*)q;
}

// ---------------------------------------------------------------------------
// Kernel 2: corr = svd_up[O,32] @ svd_down[32,I]  (fp32), 64x64 tiles
// ---------------------------------------------------------------------------
__global__ void __launch_bounds__(256) k_corr(const float* __restrict__ up,
                                              const float* __restrict__ down) {
    __shared__ float su[64][33];
    __shared__ float sd[32][65];
    const int i0 = blockIdx.x * 64, o0 = blockIdx.y * 64;
    const int t = threadIdx.x;

    for (int j = t; j < 64 * 32; j += 256)
        su[j >> 5][j & 31] = up[(size_t)(o0 + (j >> 5)) * 32 + (j & 31)];
    for (int j = t; j < 32 * 64; j += 256)
        sd[j >> 6][j & 63] = down[(size_t)(j >> 6) * IDIM + i0 + (j & 63)];
    __syncthreads();

    const int ti = (t & 15) * 4, to = (t >> 4) * 4;
    float acc[4][4] = {};
    #pragma unroll
    for (int r = 0; r < 32; r++) {
        float ua[4], db[4];
        #pragma unroll
        for (int a = 0; a < 4; a++) ua[a] = su[to + a][r];
        #pragma unroll
        for (int b = 0; b < 4; b++) db[b] = sd[r][ti + b];
        #pragma unroll
        for (int a = 0; a < 4; a++)
            #pragma unroll
            for (int b = 0; b < 4; b++) acc[a][b] += ua[a] * db[b];
    }
    #pragma unroll
    for (int a = 0; a < 4; a++) {
        float4 v = make_float4(acc[a][0], acc[a][1], acc[a][2], acc[a][3]);
        *(float4*)(g_corr + (size_t)(o0 + to + a) * IDIM + i0 + ti) = v;
    }
}

// ---------------------------------------------------------------------------
// Kernel 3: dequant W row, row max -> g_sw[o], quant -> g_Wq (int8)
// ---------------------------------------------------------------------------
__global__ void __launch_bounds__(256) k_quant_w(const int* __restrict__ wp,
                                                 const float* __restrict__ scale,
                                                 const float* __restrict__ zp) {
    const int o = blockIdx.x, t = threadIdx.x;
    const int4* pr = (const int4*)(wp + (size_t)o * 2048);
    int4 p0 = pr[2 * t], p1 = pr[2 * t + 1];
    int bv[8] = {p0.x, p0.y, p0.z, p0.w, p1.x, p1.y, p1.z, p1.w};

    const int g = t >> 2;
    const float z  = zp[o * 64 + g];
    const float sc = scale[o * 64 + g];

    const float4* cr = (const float4*)(g_corr + (size_t)o * IDIM + t * 16);
    float4 c0 = cr[0], c1 = cr[1], c2 = cr[2], c3 = cr[3];
    float cv[16] = {c0.x, c0.y, c0.z, c0.w, c1.x, c1.y, c1.z, c1.w,
                    c2.x, c2.y, c2.z, c2.w, c3.x, c3.y, c3.z, c3.w};

    float w[16];
    float m = 0.f;
    #pragma unroll
    for (int j = 0; j < 8; j++) {
        float qlo = (float)(bv[j] & 0xF);
        float qhi = (float)((bv[j] >> 4) & 0xF);
        w[2 * j]     = (qlo - z) * sc + cv[2 * j];
        w[2 * j + 1] = (qhi - z) * sc + cv[2 * j + 1];
        m = fmaxf(m, fmaxf(fabsf(w[2 * j]), fabsf(w[2 * j + 1])));
    }

    __shared__ float red[8];
    __shared__ float s_inv;
    #pragma unroll
    for (int off = 16; off; off >>= 1) m = fmaxf(m, __shfl_xor_sync(0xFFFFFFFFu, m, off));
    if ((t & 31) == 0) red[t >> 5] = m;
    __syncthreads();
    if (t == 0) {
        float mm = red[0];
        #pragma unroll
        for (int k = 1; k < 8; k++) mm = fmaxf(mm, red[k]);
        float sv = mm / 127.0f;
        g_sw[o] = sv;
        s_inv = 1.0f / sv;
    }
    __syncthreads();
    float inv = s_inv;

    alignas(16) int8_t q[16];
    #pragma unroll
    for (int k = 0; k < 16; k++) {
        float r = rintf(w[k] * inv);
        r = fminf(fmaxf(r, -128.f), 127.f);
        q[k] = (int8_t)(int)r;
    }
    *(int4*)(g_Wq + (size_t)o * IDIM + t * 16) = *(const int4*)q;
}

// ---------------------------------------------------------------------------
// Kernel 4: hybrid int8 GEMM, CTA 128x128, BK=64, 4-stage cp.async pipeline,
//   256 threads, TWO CTAs per SM (launch_bounds(256,2)), spill-free mainloop:
//   tensor path buffers a per-mi (4 regs); dp4a path buffers b per-j (4 regs).
//   Warps 0-3: mma.sync, cols 0..63 (2m x 2n, warp tile 64x32).
//   Warps 4-7: dp4a, cols 64..127; rows {q,q+8,q+16,q+24}, cols {64+c4+4cj}.
//   Both paths exact int32; epilogue reloads scales via __ldg (no live arrays).
// ---------------------------------------------------------------------------
#define STAGES 4
#define GEMM_SMEM (STAGES * 16384)     // A 8KB + B 8KB per stage = 64 KB

__global__ void __launch_bounds__(256, 2) k_gemm(const float* __restrict__ bias,
                                                 float* __restrict__ out) {
    extern __shared__ int8_t smem[];
    const uint32_t sb = smem_u32(smem);
    const int t = threadIdx.x, lane = t & 31, wid = t >> 5;
    const int m0 = blockIdx.y * 128, o0 = blockIdx.x * 128;

    const int8_t* gA = g_Xq + (size_t)m0 * IDIM;
    const int8_t* gB = g_Wq + (size_t)o0 * IDIM;

    // ---- per-thread cp.async coordinates (2 x 16B chunks per matrix) ----
    uint32_t dstOff[2], srcOff[2];
    #pragma unroll
    for (int qq = 0; qq < 2; qq++) {
        int idx = t + qq * 256;
        int r = idx >> 2, c = idx & 3;
        dstOff[qq] = r * 64 + ((c ^ ((r >> 1) & 3)) << 4);
        srcOff[qq] = r * IDIM + c * 16;
    }

    auto load_stage = [&](int kt, int s) {
        const uint32_t aB = sb + (uint32_t)s * 8192;
        const uint32_t bB = sb + STAGES * 8192 + (uint32_t)s * 8192;
        const uint32_t kb = (uint32_t)kt * 64;
        #pragma unroll
        for (int qq = 0; qq < 2; qq++)
            cp_async16(aB + dstOff[qq], gA + srcOff[qq] + kb);
        #pragma unroll
        for (int qq = 0; qq < 2; qq++)
            cp_async16(bB + dstOff[qq], gB + srcOff[qq] + kb);
        asm volatile("cp.async.commit_group;" ::: "memory");
    };

    // =========== tensor-warp state (wid 0..3): 2(m) x 2(n) grid ===========
    const int wm = (wid >> 1) & 1, wn = wid & 1;
    uint32_t adA[4][2], adB[2][2];
    int accT[4][4][4] = {};
    if (wid < 4) {
        const int lrA = lane & 15;
        const int hiA = (lane >> 4) & 1;
        #pragma unroll
        for (int mi = 0; mi < 4; mi++) {
            int row = wm * 64 + mi * 16 + lrA;
            #pragma unroll
            for (int ks = 0; ks < 2; ks++) {
                int c = ks * 2 + hiA;
                adA[mi][ks] = row * 64 + ((c ^ ((row >> 1) & 3)) << 4);
            }
        }
        const int nb = wn * 32 + ((lane >> 4) & 1) * 8 + (lane & 7);
        const int hiB = (lane >> 3) & 1;
        #pragma unroll
        for (int p = 0; p < 2; p++) {
            int n = nb + p * 16;
            #pragma unroll
            for (int ks = 0; ks < 2; ks++) {
                int c = ks * 2 + hiB;
                adB[p][ks] = STAGES * 8192 + n * 64 + ((c ^ ((n >> 1) & 3)) << 4);
            }
        }
    }

    // =========== dp4a-warp state (wid 4..7): 32 rows x 64 cols =============
    const int wd = wid - 4;
    const int q = lane >> 2;          // 0..7
    const int c4 = lane & 3;
    const int kq = (q >> 1) & 3;      // A swizzle key, ri-invariant
    const int hB = c4 >> 1;
    uint32_t aOff[4];
    int accD[4][16] = {};
    #pragma unroll
    for (int ri = 0; ri < 4; ri++)
        aOff[ri] = (uint32_t)(wd * 32 + q + 8 * ri) * 64;
    const uint32_t bColRel = (uint32_t)(STAGES * 8192) + (uint32_t)(64 + c4) * 64;

    // ---- prologue: prime 3 stages ----
    load_stage(0, 0);
    load_stage(1, 1);
    load_stage(2, 2);

    #pragma unroll 1
    for (int kt = 0; kt < 64; kt++) {
        const int s = kt & 3;
        if (kt <= 61)      asm volatile("cp.async.wait_group 2;" ::: "memory");
        else if (kt == 62) asm volatile("cp.async.wait_group 1;" ::: "memory");
        else               asm volatile("cp.async.wait_group 0;" ::: "memory");
        __syncthreads();

        if (kt + 3 < 64) load_stage(kt + 3, (kt + 3) & 3);

        const uint32_t sOff = sb + (uint32_t)s * 8192;

        if (wid < 4) {
            // ---------------- tensor path: cols 0..63 ----------------
            // b loaded once per ks (8 regs); a streamed per-mi (4 regs).
            #pragma unroll
            for (int ks = 0; ks < 2; ks++) {
                uint32_t b[2][4];
                ldsm4(b[0], sOff + adB[0][ks]);
                ldsm4(b[1], sOff + adB[1][ks]);
                #pragma unroll
                for (int mi = 0; mi < 4; mi++) {
                    uint32_t a4[4];
                    ldsm4(a4, sOff + adA[mi][ks]);
                    mma_s8(accT[mi][0], a4, b[0]);
                    mma_s8(accT[mi][1], a4, b[0] + 2);
                    mma_s8(accT[mi][2], a4, b[1]);
                    mma_s8(accT[mi][3], a4, b[1] + 2);
                }
            }
        } else {
            // ---------------- dp4a path: cols 64..127 ----------------
            // a[4][4] resident per cgi; b streamed per-j (4 regs).
            const uint32_t bCB = sOff + bColRel;
            #pragma unroll
            for (int cgi = 0; cgi < 4; cgi++) {
                const uint32_t aBase = sOff + (uint32_t)(((cgi ^ kq) & 3) << 4);
                uint32_t a[4][4];
                #pragma unroll
                for (int ri = 0; ri < 4; ri++)
                    lds128(a[ri], aBase + aOff[ri]);
                const uint32_t be = bCB + (uint32_t)(((cgi ^ hB) & 3) << 4);
                const uint32_t bo = be ^ 0x20u;
                #pragma unroll
                for (int cj = 0; cj < 16; cj++) {
                    uint32_t bb4[4];
                    lds128(bb4, ((cj & 1) ? bo : be) + (uint32_t)cj * 256);
                    #pragma unroll
                    for (int kk = 0; kk < 4; kk++)
                        #pragma unroll
                        for (int ri = 0; ri < 4; ri++)
                            accD[ri][cj] =
                                __dp4a((int)a[ri][kk], (int)bb4[kk], accD[ri][cj]);
                }
            }
        }
    }

    // ---- fused epilogue: out = float(acc) * sx[row] * sw[col] + bias[col] ----
    if (wid < 4) {
        const int r0 = lane >> 2;
        const int cq = (lane & 3) * 2;
        #pragma unroll
        for (int mi = 0; mi < 4; mi++) {
            #pragma unroll
            for (int h = 0; h < 2; h++) {
                int row = m0 + wm * 64 + mi * 16 + r0 + 8 * h;
                float sx = g_sx[row];
                float* op = out + (size_t)row * ODIM + o0 + wn * 32 + cq;
                #pragma unroll
                for (int ni = 0; ni < 4; ni++) {
                    int co = o0 + wn * 32 + ni * 8 + cq;
                    float2 v;
                    v.x = (float)accT[mi][ni][2 * h]     * sx * __ldg(&g_sw[co])
                          + __ldg(&bias[co]);
                    v.y = (float)accT[mi][ni][2 * h + 1] * sx * __ldg(&g_sw[co + 1])
                          + __ldg(&bias[co + 1]);
                    *(float2*)(op + ni * 8) = v;
                }
            }
        }
    } else {
        const int cb = o0 + 64 + c4;
        #pragma unroll
        for (int ri = 0; ri < 4; ri++) {
            int row = m0 + wd * 32 + q + 8 * ri;
            float sx = g_sx[row];
            float* op = out + (size_t)row * ODIM + cb;
            #pragma unroll
            for (int cj = 0; cj < 16; cj++) {
                int co = cb + 4 * cj;
                op[4 * cj] = (float)accD[ri][cj] * sx * __ldg(&g_sw[co])
                             + __ldg(&bias[co]);
            }
        }
    }
}

// ---------------------------------------------------------------------------
extern "C" void kernel_launch(void* const* d_in, const int* in_sizes, int n_in,
                              void* d_out, int out_size) {
    const float* x     = (const float*)d_in[0];
    const int*   wp    = (const int*)  d_in[1];
    const float* up    = (const float*)d_in[2];
    const float* down  = (const float*)d_in[3];
    const float* scale = (const float*)d_in[4];
    const float* zp    = (const float*)d_in[5];
    const float* bias  = (const float*)d_in[6];
    float* out = (float*)d_out;

    k_quant_x<<<NTOK, 256>>>(x);
    k_corr<<<dim3(IDIM / 64, ODIM / 64), 256>>>(up, down);
    k_quant_w<<<ODIM, 256>>>(wp, scale, zp);

    static int smem_set = 0;
    if (!smem_set) {
        cudaFuncSetAttribute(k_gemm, cudaFuncAttributeMaxDynamicSharedMemorySize,
                             GEMM_SMEM);
        smem_set = 1;
    }
    k_gemm<<<dim3(ODIM / 128, NTOK / 128), 256, GEMM_SMEM>>>(bias, out);
}

// round 14
// speedup vs baseline: 1.0915x; 1.0915x over previous
#include <cuda_runtime.h>
#include <cuda_bf16.h>
#include <cstdint>
#include <cstddef>

// ============================================================================
// HQQSVDLinear forward_int8 on GB300 (sm_103 base ISA; tcgen05 blocked by
// toolchain — R6). R7 pure mma.sync 926us. R8 specialized hybrid 742us
// (latency-bound). R12/R13: 2-CTA attempts spilled (~140 regs needed by
// specialized warps). R14: MERGED warps — every warp does mma (cols 0..47)
// AND dp4a (cols 48..127) on its own 16-row slice. Halved accumulator state
// (~115 regs) fits launch_bounds(256,2) without spills; dp4a stream fills
// every mma/LDS stall. Both paths accumulate exact int32 vs the reference.
// ============================================================================

#define NTOK 4096
#define ODIM 4096
#define IDIM 4096

__device__ int8_t g_Xq[(size_t)NTOK * IDIM];          // 16 MB
__device__ int8_t g_Wq[(size_t)ODIM * IDIM];          // 16 MB
__device__ float  g_corr[(size_t)ODIM * IDIM];        // 64 MB
__device__ float  g_sx[NTOK];
__device__ float  g_sw[ODIM];

// ---------------------------------------------------------------------------
__device__ __forceinline__ uint32_t smem_u32(const void* p) {
    uint32_t a;
    asm("{ .reg .u64 t; cvta.to.shared.u64 t, %1; cvt.u32.u64 %0, t; }"
        : "=r"(a) : "l"(p));
    return a;
}

__device__ __forceinline__ void cp_async16(uint32_t dst, const void* src) {
    asm volatile("cp.async.cg.shared.global [%0], [%1], 16;"
                 :: "r"(dst), "l"(src) : "memory");
}

__device__ __forceinline__ void ldsm4(uint32_t* r, uint32_t addr) {
    asm volatile("ldmatrix.sync.aligned.m8n8.x4.shared.b16 {%0,%1,%2,%3}, [%4];"
                 : "=r"(r[0]), "=r"(r[1]), "=r"(r[2]), "=r"(r[3]) : "r"(addr));
}

__device__ __forceinline__ void lds128(uint32_t* r, uint32_t addr) {
    asm volatile("ld.shared.v4.b32 {%0,%1,%2,%3}, [%4];"
                 : "=r"(r[0]), "=r"(r[1]), "=r"(r[2]), "=r"(r[3]) : "r"(addr));
}

__device__ __forceinline__ void mma_s8(int* c, const uint32_t* a, const uint32_t* b) {
    asm volatile(
        "mma.sync.aligned.m16n8k32.row.col.s32.s8.s8.s32 "
        "{%0,%1,%2,%3}, {%4,%5,%6,%7}, {%8,%9}, {%0,%1,%2,%3};"
        : "+r"(c[0]), "+r"(c[1]), "+r"(c[2]), "+r"(c[3])
        : "r"(a[0]), "r"(a[1]), "r"(a[2]), "r"(a[3]), "r"(b[0]), "r"(b[1]));
}

// ---------------------------------------------------------------------------
// Kernel 1: per-token activation quant.  x[n,:] -> g_Xq (int8), g_sx[n]
// ---------------------------------------------------------------------------
__global__ void __launch_bounds__(256) k_quant_x(const float* __restrict__ x) {
    const int n = blockIdx.x, t = threadIdx.x;
    const float4* xr = (const float4*)(x + (size_t)n * IDIM) + t * 4;
    float v[16];
    float4 a0 = xr[0], a1 = xr[1], a2 = xr[2], a3 = xr[3];
    v[0]=a0.x; v[1]=a0.y; v[2]=a0.z; v[3]=a0.w;
    v[4]=a1.x; v[5]=a1.y; v[6]=a1.z; v[7]=a1.w;
    v[8]=a2.x; v[9]=a2.y; v[10]=a2.z; v[11]=a2.w;
    v[12]=a3.x; v[13]=a3.y; v[14]=a3.z; v[15]=a3.w;

    float m = 0.f;
    #pragma unroll
    for (int k = 0; k < 16; k++) m = fmaxf(m, fabsf(v[k]));

    __shared__ float red[8];
    __shared__ float s_inv;
    #pragma unroll
    for (int off = 16; off; off >>= 1) m = fmaxf(m, __shfl_xor_sync(0xFFFFFFFFu, m, off));
    if ((t & 31) == 0) red[t >> 5] = m;
    __syncthreads();
    if (t == 0) {
        float mm = red[0];
        #pragma unroll
        for (int k = 1; k < 8; k++) mm = fmaxf(mm, red[k]);
        float sv = mm / 127.0f;
        g_sx[n] = sv;
        s_inv = 1.0f / sv;
    }
    __syncthreads();
    float inv = s_inv;

    alignas(16) int8_t q[16];
    #pragma unroll
    for (int k = 0; k < 16; k++) {
        float r = rintf(v[k] * inv);
        r = fminf(fmaxf(r, -128.f), 127.f);
        q[k] = (int8_t)(int)r;
    }
    *(int4*)(g_Xq + (size_t)n * IDIM + t * 16) = *(const int4*)q;
}

// ---------------------------------------------------------------------------
// Kernel 2: corr = svd_up[O,32] @ svd_down[32,I]  (fp32), 64x64 tiles
// ---------------------------------------------------------------------------
__global__ void __launch_bounds__(256) k_corr(const float* __restrict__ up,
                                              const float* __restrict__ down) {
    __shared__ float su[64][33];
    __shared__ float sd[32][65];
    const int i0 = blockIdx.x * 64, o0 = blockIdx.y * 64;
    const int t = threadIdx.x;

    for (int j = t; j < 64 * 32; j += 256)
        su[j >> 5][j & 31] = up[(size_t)(o0 + (j >> 5)) * 32 + (j & 31)];
    for (int j = t; j < 32 * 64; j += 256)
        sd[j >> 6][j & 63] = down[(size_t)(j >> 6) * IDIM + i0 + (j & 63)];
    __syncthreads();

    const int ti = (t & 15) * 4, to = (t >> 4) * 4;
    float acc[4][4] = {};
    #pragma unroll
    for (int r = 0; r < 32; r++) {
        float ua[4], db[4];
        #pragma unroll
        for (int a = 0; a < 4; a++) ua[a] = su[to + a][r];
        #pragma unroll
        for (int b = 0; b < 4; b++) db[b] = sd[r][ti + b];
        #pragma unroll
        for (int a = 0; a < 4; a++)
            #pragma unroll
            for (int b = 0; b < 4; b++) acc[a][b] += ua[a] * db[b];
    }
    #pragma unroll
    for (int a = 0; a < 4; a++) {
        float4 v = make_float4(acc[a][0], acc[a][1], acc[a][2], acc[a][3]);
        *(float4*)(g_corr + (size_t)(o0 + to + a) * IDIM + i0 + ti) = v;
    }
}

// ---------------------------------------------------------------------------
// Kernel 3: dequant W row, row max -> g_sw[o], quant -> g_Wq (int8)
// ---------------------------------------------------------------------------
__global__ void __launch_bounds__(256) k_quant_w(const int* __restrict__ wp,
                                                 const float* __restrict__ scale,
                                                 const float* __restrict__ zp) {
    const int o = blockIdx.x, t = threadIdx.x;
    const int4* pr = (const int4*)(wp + (size_t)o * 2048);
    int4 p0 = pr[2 * t], p1 = pr[2 * t + 1];
    int bv[8] = {p0.x, p0.y, p0.z, p0.w, p1.x, p1.y, p1.z, p1.w};

    const int g = t >> 2;
    const float z  = zp[o * 64 + g];
    const float sc = scale[o * 64 + g];

    const float4* cr = (const float4*)(g_corr + (size_t)o * IDIM + t * 16);
    float4 c0 = cr[0], c1 = cr[1], c2 = cr[2], c3 = cr[3];
    float cv[16] = {c0.x, c0.y, c0.z, c0.w, c1.x, c1.y, c1.z, c1.w,
                    c2.x, c2.y, c2.z, c2.w, c3.x, c3.y, c3.z, c3.w};

    float w[16];
    float m = 0.f;
    #pragma unroll
    for (int j = 0; j < 8; j++) {
        float qlo = (float)(bv[j] & 0xF);
        float qhi = (float)((bv[j] >> 4) & 0xF);
        w[2 * j]     = (qlo - z) * sc + cv[2 * j];
        w[2 * j + 1] = (qhi - z) * sc + cv[2 * j + 1];
        m = fmaxf(m, fmaxf(fabsf(w[2 * j]), fabsf(w[2 * j + 1])));
    }

    __shared__ float red[8];
    __shared__ float s_inv;
    #pragma unroll
    for (int off = 16; off; off >>= 1) m = fmaxf(m, __shfl_xor_sync(0xFFFFFFFFu, m, off));
    if ((t & 31) == 0) red[t >> 5] = m;
    __syncthreads();
    if (t == 0) {
        float mm = red[0];
        #pragma unroll
        for (int k = 1; k < 8; k++) mm = fmaxf(mm, red[k]);
        float sv = mm / 127.0f;
        g_sw[o] = sv;
        s_inv = 1.0f / sv;
    }
    __syncthreads();
    float inv = s_inv;

    alignas(16) int8_t q[16];
    #pragma unroll
    for (int k = 0; k < 16; k++) {
        float r = rintf(w[k] * inv);
        r = fminf(fmaxf(r, -128.f), 127.f);
        q[k] = (int8_t)(int)r;
    }
    *(int4*)(g_Wq + (size_t)o * IDIM + t * 16) = *(const int4*)q;
}

// ---------------------------------------------------------------------------
// Kernel 4: MERGED hybrid int8 GEMM, CTA 128x128, BK=64, 4-stage cp.async,
//   256 threads, launch_bounds(256,2). Every warp owns rows wid*16..+16 and:
//     - mma.sync over cols 0..47  (1 m16 x 6 n8 tiles x 2 ks = 12 mma/iter)
//     - dp4a    over cols 48..127 (rows {q,q+8}, cols {48+c4+4cj, cj<20})
//   The dp4a stream (640/iter) fills issue slots while mma/ldsm results are
//   in flight. Both paths exact int32; fused float epilogue via __ldg.
// ---------------------------------------------------------------------------
#define STAGES 4
#define GEMM_SMEM (STAGES * 16384)     // A 8KB + B 8KB per stage = 64 KB

__global__ void __launch_bounds__(256, 2) k_gemm(const float* __restrict__ bias,
                                                 float* __restrict__ out) {
    extern __shared__ int8_t smem[];
    const uint32_t sb = smem_u32(smem);
    const int t = threadIdx.x, lane = t & 31, wid = t >> 5;
    const int m0 = blockIdx.y * 128, o0 = blockIdx.x * 128;

    const int8_t* gA = g_Xq + (size_t)m0 * IDIM;
    const int8_t* gB = g_Wq + (size_t)o0 * IDIM;

    // ---- per-thread cp.async coordinates (2 x 16B chunks per matrix) ----
    uint32_t dstOff[2], srcOff[2];
    #pragma unroll
    for (int qq = 0; qq < 2; qq++) {
        int idx = t + qq * 256;
        int r = idx >> 2, c = idx & 3;
        dstOff[qq] = r * 64 + ((c ^ ((r >> 1) & 3)) << 4);
        srcOff[qq] = r * IDIM + c * 16;
    }

    auto load_stage = [&](int kt, int s) {
        const uint32_t aB = sb + (uint32_t)s * 8192;
        const uint32_t bB = sb + STAGES * 8192 + (uint32_t)s * 8192;
        const uint32_t kb = (uint32_t)kt * 64;
        #pragma unroll
        for (int qq = 0; qq < 2; qq++)
            cp_async16(aB + dstOff[qq], gA + srcOff[qq] + kb);
        #pragma unroll
        for (int qq = 0; qq < 2; qq++)
            cp_async16(bB + dstOff[qq], gB + srcOff[qq] + kb);
        asm volatile("cp.async.commit_group;" ::: "memory");
    };

    // ---- tensor addressing: A m16 slice (rows wid*16..+16), B cols 0..47 ----
    uint32_t adA[2], adB[3][2];
    {
        const int rowA = wid * 16 + (lane & 15);
        const int hiA = (lane >> 4) & 1;
        #pragma unroll
        for (int ks = 0; ks < 2; ks++) {
            int c = ks * 2 + hiA;
            adA[ks] = rowA * 64 + ((c ^ ((rowA >> 1) & 3)) << 4);
        }
        const int nb = ((lane >> 4) & 1) * 8 + (lane & 7);
        const int hiB = (lane >> 3) & 1;
        #pragma unroll
        for (int p = 0; p < 3; p++) {
            int n = nb + p * 16;
            #pragma unroll
            for (int ks = 0; ks < 2; ks++) {
                int c = ks * 2 + hiB;
                adB[p][ks] = STAGES * 8192 + n * 64 + ((c ^ ((n >> 1) & 3)) << 4);
            }
        }
    }
    int accT[6][4] = {};

    // ---- dp4a addressing: rows {wid*16+q, wid*16+q+8}, cols 48..127 ----
    const int q = lane >> 2;          // 0..7
    const int c4 = lane & 3;
    const int kq = (q >> 1) & 3;      // A swizzle key, same for both rows
    const int hB = c4 >> 1;
    uint32_t aOff[2];
    aOff[0] = (uint32_t)(wid * 16 + q) * 64;
    aOff[1] = (uint32_t)(wid * 16 + q + 8) * 64;
    const uint32_t bColRel = (uint32_t)(STAGES * 8192) + (uint32_t)(48 + c4) * 64;
    int accD[2][20] = {};

    // ---- prologue: prime 3 stages ----
    load_stage(0, 0);
    load_stage(1, 1);
    load_stage(2, 2);

    #pragma unroll 1
    for (int kt = 0; kt < 64; kt++) {
        const int s = kt & 3;
        if (kt <= 61)      asm volatile("cp.async.wait_group 2;" ::: "memory");
        else if (kt == 62) asm volatile("cp.async.wait_group 1;" ::: "memory");
        else               asm volatile("cp.async.wait_group 0;" ::: "memory");
        __syncthreads();

        if (kt + 3 < 64) load_stage(kt + 3, (kt + 3) & 3);

        const uint32_t sOff = sb + (uint32_t)s * 8192;

        // ---------------- tensor part: cols 0..47 ----------------
        #pragma unroll
        for (int ks = 0; ks < 2; ks++) {
            uint32_t a4[4], b0[4], b1[4], b2[4];
            ldsm4(a4, sOff + adA[ks]);
            ldsm4(b0, sOff + adB[0][ks]);
            ldsm4(b1, sOff + adB[1][ks]);
            ldsm4(b2, sOff + adB[2][ks]);
            mma_s8(accT[0], a4, b0);
            mma_s8(accT[1], a4, b0 + 2);
            mma_s8(accT[2], a4, b1);
            mma_s8(accT[3], a4, b1 + 2);
            mma_s8(accT[4], a4, b2);
            mma_s8(accT[5], a4, b2 + 2);
        }

        // ---------------- dp4a part: cols 48..127 ----------------
        const uint32_t bCB = sOff + bColRel;
        #pragma unroll
        for (int cgi = 0; cgi < 4; cgi++) {
            const uint32_t aBase = sOff + (uint32_t)(((cgi ^ kq) & 3) << 4);
            uint32_t a[2][4];
            lds128(a[0], aBase + aOff[0]);
            lds128(a[1], aBase + aOff[1]);
            const uint32_t be = bCB + (uint32_t)(((cgi ^ hB) & 3) << 4);
            const uint32_t bo = be ^ 0x20u;
            #pragma unroll
            for (int cj = 0; cj < 20; cj++) {
                uint32_t bb4[4];
                lds128(bb4, ((cj & 1) ? bo : be) + (uint32_t)cj * 256);
                #pragma unroll
                for (int kk = 0; kk < 4; kk++) {
                    accD[0][cj] = __dp4a((int)a[0][kk], (int)bb4[kk], accD[0][cj]);
                    accD[1][cj] = __dp4a((int)a[1][kk], (int)bb4[kk], accD[1][cj]);
                }
            }
        }
    }

    // ---- fused epilogue: out = float(acc) * sx[row] * sw[col] + bias[col] ----
    {
        // tensor half: rows wid*16 + {r0, r0+8}, cols o0 + ni*8 + cq
        const int r0 = lane >> 2;
        const int cq = (lane & 3) * 2;
        #pragma unroll
        for (int h = 0; h < 2; h++) {
            int row = m0 + wid * 16 + r0 + 8 * h;
            float sx = g_sx[row];
            float* op = out + (size_t)row * ODIM + o0 + cq;
            #pragma unroll
            for (int ni = 0; ni < 6; ni++) {
                int co = o0 + ni * 8 + cq;
                float2 v;
                v.x = (float)accT[ni][2 * h]     * sx * __ldg(&g_sw[co])
                      + __ldg(&bias[co]);
                v.y = (float)accT[ni][2 * h + 1] * sx * __ldg(&g_sw[co + 1])
                      + __ldg(&bias[co + 1]);
                *(float2*)(op + ni * 8) = v;
            }
        }
        // dp4a half: rows wid*16 + {q, q+8}, cols o0 + 48 + c4 + 4*cj
        const int cb = o0 + 48 + c4;
        #pragma unroll
        for (int ri = 0; ri < 2; ri++) {
            int row = m0 + wid * 16 + q + 8 * ri;
            float sx = g_sx[row];
            float* op = out + (size_t)row * ODIM + cb;
            #pragma unroll
            for (int cj = 0; cj < 20; cj++) {
                int co = cb + 4 * cj;
                op[4 * cj] = (float)accD[ri][cj] * sx * __ldg(&g_sw[co])
                             + __ldg(&bias[co]);
            }
        }
    }
}

// ---------------------------------------------------------------------------
extern "C" void kernel_launch(void* const* d_in, const int* in_sizes, int n_in,
                              void* d_out, int out_size) {
    const float* x     = (const float*)d_in[0];
    const int*   wp    = (const int*)  d_in[1];
    const float* up    = (const float*)d_in[2];
    const float* down  = (const float*)d_in[3];
    const float* scale = (const float*)d_in[4];
    const float* zp    = (const float*)d_in[5];
    const float* bias  = (const float*)d_in[6];
    float* out = (float*)d_out;

    k_quant_x<<<NTOK, 256>>>(x);
    k_corr<<<dim3(IDIM / 64, ODIM / 64), 256>>>(up, down);
    k_quant_w<<<ODIM, 256>>>(wp, scale, zp);

    static int smem_set = 0;
    if (!smem_set) {
        cudaFuncSetAttribute(k_gemm, cudaFuncAttributeMaxDynamicSharedMemorySize,
                             GEMM_SMEM);
        smem_set = 1;
    }
    k_gemm<<<dim3(ODIM / 128, NTOK / 128), 256, GEMM_SMEM>>>(bias, out);
}

// round 15
// speedup vs baseline: 1.2267x; 1.1239x over previous
#include <cuda_runtime.h>
#include <cuda_bf16.h>
#include <cstdint>
#include <cstddef>

// ============================================================================
// HQQSVDLinear forward_int8 on GB300 (sm_103 base ISA; tcgen05 blocked by
// toolchain — R6). Measured facts: R7 (8 tensor warps, 2/SMSP) -> tensor pipe
// 93.6% (~275 MACs/cyc/SM cap). R8 (1T+1D per SMSP) -> tensor starved at 62%,
// dp4a ~174 MACs/cyc/SM, L1 54%. >4 dp4a-streaming warps/SM -> crossbar wall
// (R10/R14 L1 ~81%).
// R15: 384-thread CTA, 12 warps: 8 tensor (2/SMSP, cols 0..79, 32x40 tiles)
// + 4 dp4a (1/SMSP, cols 80..127, R8 mapping). Split 80:48 = measured 258:174.
// Both paths accumulate exact int32 vs the reference GEMM.
// ============================================================================

#define NTOK 4096
#define ODIM 4096
#define IDIM 4096

__device__ int8_t g_Xq[(size_t)NTOK * IDIM];          // 16 MB
__device__ int8_t g_Wq[(size_t)ODIM * IDIM];          // 16 MB
__device__ float  g_corr[(size_t)ODIM * IDIM];        // 64 MB
__device__ float  g_sx[NTOK];
__device__ float  g_sw[ODIM];

// ---------------------------------------------------------------------------
__device__ __forceinline__ uint32_t smem_u32(const void* p) {
    uint32_t a;
    asm("{ .reg .u64 t; cvta.to.shared.u64 t, %1; cvt.u32.u64 %0, t; }"
        : "=r"(a) : "l"(p));
    return a;
}

__device__ __forceinline__ void cp_async16(uint32_t dst, const void* src) {
    asm volatile("cp.async.cg.shared.global [%0], [%1], 16;"
                 :: "r"(dst), "l"(src) : "memory");
}

__device__ __forceinline__ void ldsm4(uint32_t* r, uint32_t addr) {
    asm volatile("ldmatrix.sync.aligned.m8n8.x4.shared.b16 {%0,%1,%2,%3}, [%4];"
                 : "=r"(r[0]), "=r"(r[1]), "=r"(r[2]), "=r"(r[3]) : "r"(addr));
}

__device__ __forceinline__ void ldsm2(uint32_t* r, uint32_t addr) {
    asm volatile("ldmatrix.sync.aligned.m8n8.x2.shared.b16 {%0,%1}, [%2];"
                 : "=r"(r[0]), "=r"(r[1]) : "r"(addr));
}

__device__ __forceinline__ void lds128(uint32_t* r, uint32_t addr) {
    asm volatile("ld.shared.v4.b32 {%0,%1,%2,%3}, [%4];"
                 : "=r"(r[0]), "=r"(r[1]), "=r"(r[2]), "=r"(r[3]) : "r"(addr));
}

__device__ __forceinline__ void mma_s8(int* c, const uint32_t* a, const uint32_t* b) {
    asm volatile(
        "mma.sync.aligned.m16n8k32.row.col.s32.s8.s8.s32 "
        "{%0,%1,%2,%3}, {%4,%5,%6,%7}, {%8,%9}, {%0,%1,%2,%3};"
        : "+r"(c[0]), "+r"(c[1]), "+r"(c[2]), "+r"(c[3])
        : "r"(a[0]), "r"(a[1]), "r"(a[2]), "r"(a[3]), "r"(b[0]), "r"(b[1]));
}

// ---------------------------------------------------------------------------
// Kernel 1: per-token activation quant.  x[n,:] -> g_Xq (int8), g_sx[n]
// ---------------------------------------------------------------------------
__global__ void __launch_bounds__(256) k_quant_x(const float* __restrict__ x) {
    const int n = blockIdx.x, t = threadIdx.x;
    const float4* xr = (const float4*)(x + (size_t)n * IDIM) + t * 4;
    float v[16];
    float4 a0 = xr[0], a1 = xr[1], a2 = xr[2], a3 = xr[3];
    v[0]=a0.x; v[1]=a0.y; v[2]=a0.z; v[3]=a0.w;
    v[4]=a1.x; v[5]=a1.y; v[6]=a1.z; v[7]=a1.w;
    v[8]=a2.x; v[9]=a2.y; v[10]=a2.z; v[11]=a2.w;
    v[12]=a3.x; v[13]=a3.y; v[14]=a3.z; v[15]=a3.w;

    float m = 0.f;
    #pragma unroll
    for (int k = 0; k < 16; k++) m = fmaxf(m, fabsf(v[k]));

    __shared__ float red[8];
    __shared__ float s_inv;
    #pragma unroll
    for (int off = 16; off; off >>= 1) m = fmaxf(m, __shfl_xor_sync(0xFFFFFFFFu, m, off));
    if ((t & 31) == 0) red[t >> 5] = m;
    __syncthreads();
    if (t == 0) {
        float mm = red[0];
        #pragma unroll
        for (int k = 1; k < 8; k++) mm = fmaxf(mm, red[k]);
        float sv = mm / 127.0f;
        g_sx[n] = sv;
        s_inv = 1.0f / sv;
    }
    __syncthreads();
    float inv = s_inv;

    alignas(16) int8_t q[16];
    #pragma unroll
    for (int k = 0; k < 16; k++) {
        float r = rintf(v[k] * inv);
        r = fminf(fmaxf(r, -128.f), 127.f);
        q[k] = (int8_t)(int)r;
    }
    *(int4*)(g_Xq + (size_t)n * IDIM + t * 16) = *(const int4*)q;
}

// ---------------------------------------------------------------------------
// Kernel 2: corr = svd_up[O,32] @ svd_down[32,I]  (fp32), 64x64 tiles
// ---------------------------------------------------------------------------
__global__ void __launch_bounds__(256) k_corr(const float* __restrict__ up,
                                              const float* __restrict__ down) {
    __shared__ float su[64][33];
    __shared__ float sd[32][65];
    const int i0 = blockIdx.x * 64, o0 = blockIdx.y * 64;
    const int t = threadIdx.x;

    for (int j = t; j < 64 * 32; j += 256)
        su[j >> 5][j & 31] = up[(size_t)(o0 + (j >> 5)) * 32 + (j & 31)];
    for (int j = t; j < 32 * 64; j += 256)
        sd[j >> 6][j & 63] = down[(size_t)(j >> 6) * IDIM + i0 + (j & 63)];
    __syncthreads();

    const int ti = (t & 15) * 4, to = (t >> 4) * 4;
    float acc[4][4] = {};
    #pragma unroll
    for (int r = 0; r < 32; r++) {
        float ua[4], db[4];
        #pragma unroll
        for (int a = 0; a < 4; a++) ua[a] = su[to + a][r];
        #pragma unroll
        for (int b = 0; b < 4; b++) db[b] = sd[r][ti + b];
        #pragma unroll
        for (int a = 0; a < 4; a++)
            #pragma unroll
            for (int b = 0; b < 4; b++) acc[a][b] += ua[a] * db[b];
    }
    #pragma unroll
    for (int a = 0; a < 4; a++) {
        float4 v = make_float4(acc[a][0], acc[a][1], acc[a][2], acc[a][3]);
        *(float4*)(g_corr + (size_t)(o0 + to + a) * IDIM + i0 + ti) = v;
    }
}

// ---------------------------------------------------------------------------
// Kernel 3: dequant W row, row max -> g_sw[o], quant -> g_Wq (int8)
// ---------------------------------------------------------------------------
__global__ void __launch_bounds__(256) k_quant_w(const int* __restrict__ wp,
                                                 const float* __restrict__ scale,
                                                 const float* __restrict__ zp) {
    const int o = blockIdx.x, t = threadIdx.x;
    const int4* pr = (const int4*)(wp + (size_t)o * 2048);
    int4 p0 = pr[2 * t], p1 = pr[2 * t + 1];
    int bv[8] = {p0.x, p0.y, p0.z, p0.w, p1.x, p1.y, p1.z, p1.w};

    const int g = t >> 2;
    const float z  = zp[o * 64 + g];
    const float sc = scale[o * 64 + g];

    const float4* cr = (const float4*)(g_corr + (size_t)o * IDIM + t * 16);
    float4 c0 = cr[0], c1 = cr[1], c2 = cr[2], c3 = cr[3];
    float cv[16] = {c0.x, c0.y, c0.z, c0.w, c1.x, c1.y, c1.z, c1.w,
                    c2.x, c2.y, c2.z, c2.w, c3.x, c3.y, c3.z, c3.w};

    float w[16];
    float m = 0.f;
    #pragma unroll
    for (int j = 0; j < 8; j++) {
        float qlo = (float)(bv[j] & 0xF);
        float qhi = (float)((bv[j] >> 4) & 0xF);
        w[2 * j]     = (qlo - z) * sc + cv[2 * j];
        w[2 * j + 1] = (qhi - z) * sc + cv[2 * j + 1];
        m = fmaxf(m, fmaxf(fabsf(w[2 * j]), fabsf(w[2 * j + 1])));
    }

    __shared__ float red[8];
    __shared__ float s_inv;
    #pragma unroll
    for (int off = 16; off; off >>= 1) m = fmaxf(m, __shfl_xor_sync(0xFFFFFFFFu, m, off));
    if ((t & 31) == 0) red[t >> 5] = m;
    __syncthreads();
    if (t == 0) {
        float mm = red[0];
        #pragma unroll
        for (int k = 1; k < 8; k++) mm = fmaxf(mm, red[k]);
        float sv = mm / 127.0f;
        g_sw[o] = sv;
        s_inv = 1.0f / sv;
    }
    __syncthreads();
    float inv = s_inv;

    alignas(16) int8_t q[16];
    #pragma unroll
    for (int k = 0; k < 16; k++) {
        float r = rintf(w[k] * inv);
        r = fminf(fmaxf(r, -128.f), 127.f);
        q[k] = (int8_t)(int)r;
    }
    *(int4*)(g_Wq + (size_t)o * IDIM + t * 16) = *(const int4*)q;
}

// ---------------------------------------------------------------------------
// Kernel 4: hybrid int8 GEMM, CTA 128x128, BK=64, 4-stage cp.async, 384 thr.
//   Warps 0-7 (2/SMSP): mma.sync, cols 0..79. 4(m)x2(n) grid, tile 32x40
//     (2 m16-tiles x 5 n8-tiles; ldsm: A 2x ldsm4, B 2x ldsm4 + ldsm2 per ks).
//   Warps 8-11 (1/SMSP): dp4a, cols 80..127 (R8 mapping). Warp wd rows
//     wd*32..+32; lane (q,c4): rows {q,q+8,q+16,q+24}, cols {80+c4+4cj,cj<12}.
//   Both paths exact int32; fused float epilogue.
// ---------------------------------------------------------------------------
#define STAGES 4
#define GEMM_SMEM (STAGES * 16384)     // A 8KB + B 8KB per stage = 64 KB
#define NTHREADS 384

__global__ void __launch_bounds__(NTHREADS, 1) k_gemm(const float* __restrict__ bias,
                                                      float* __restrict__ out) {
    extern __shared__ int8_t smem[];
    const uint32_t sb = smem_u32(smem);
    const int t = threadIdx.x, lane = t & 31, wid = t >> 5;
    const int m0 = blockIdx.y * 128, o0 = blockIdx.x * 128;

    const int8_t* gA = g_Xq + (size_t)m0 * IDIM;
    const int8_t* gB = g_Wq + (size_t)o0 * IDIM;

    // ---- cp.async: 512 16B chunks per matrix, 384 threads ----
    auto load_stage = [&](int kt, int s) {
        const uint32_t aB = sb + (uint32_t)s * 8192;
        const uint32_t bB = sb + STAGES * 8192 + (uint32_t)s * 8192;
        const uint32_t kb = (uint32_t)kt * 64;
        #pragma unroll
        for (int idx = 0; idx < 2; idx++) {
            int j = t + idx * NTHREADS;
            if (j < 512) {
                int r = j >> 2, c = j & 3;
                uint32_t d = r * 64 + ((c ^ ((r >> 1) & 3)) << 4);
                uint32_t sg = r * IDIM + c * 16;
                cp_async16(aB + d, gA + sg + kb);
                cp_async16(bB + d, gB + sg + kb);
            }
        }
        asm volatile("cp.async.commit_group;" ::: "memory");
    };

    // ====== tensor-warp state (wid 0..7): 4(m) x 2(n), tile 32x40 ==========
    const int wm = wid >> 1, wn = wid & 1;       // wm 0..3, wn 0..1
    uint32_t adA[2][2], adB4[2][2], adB2[2];
    int accT[2][5][4] = {};
    if (wid < 8) {
        const int lrA = lane & 15;
        const int hiA = (lane >> 4) & 1;
        #pragma unroll
        for (int mi = 0; mi < 2; mi++) {
            int row = wm * 32 + mi * 16 + lrA;
            #pragma unroll
            for (int ks = 0; ks < 2; ks++) {
                int c = ks * 2 + hiA;
                adA[mi][ks] = row * 64 + ((c ^ ((row >> 1) & 3)) << 4);
            }
        }
        const int hiB = (lane >> 3) & 1;
        #pragma unroll
        for (int p = 0; p < 2; p++) {
            int n = wn * 40 + p * 16 + ((lane >> 4) & 1) * 8 + (lane & 7);
            #pragma unroll
            for (int ks = 0; ks < 2; ks++) {
                int c = ks * 2 + hiB;
                adB4[p][ks] = STAGES * 8192 + n * 64 + ((c ^ ((n >> 1) & 3)) << 4);
            }
        }
        {
            int n = wn * 40 + 32 + (lane & 7);
            #pragma unroll
            for (int ks = 0; ks < 2; ks++) {
                int c = ks * 2 + hiB;
                adB2[ks] = STAGES * 8192 + n * 64 + ((c ^ ((n >> 1) & 3)) << 4);
            }
        }
    }

    // ====== dp4a-warp state (wid 8..11): 32 rows x 48 cols ================
    const int wd = wid - 8;
    const int q = lane >> 2;          // 0..7
    const int c4 = lane & 3;
    const int kq = (q >> 1) & 3;      // A swizzle key, ri-invariant
    const int hB = c4 >> 1;
    uint32_t aOff[4];
    int accD[4][12] = {};
    #pragma unroll
    for (int ri = 0; ri < 4; ri++)
        aOff[ri] = (uint32_t)(wd * 32 + q + 8 * ri) * 64;
    const uint32_t bColRel = (uint32_t)(STAGES * 8192) + (uint32_t)(80 + c4) * 64;

    // ---- prologue: prime 3 stages ----
    load_stage(0, 0);
    load_stage(1, 1);
    load_stage(2, 2);

    #pragma unroll 1
    for (int kt = 0; kt < 64; kt++) {
        const int s = kt & 3;
        if (kt <= 61)      asm volatile("cp.async.wait_group 2;" ::: "memory");
        else if (kt == 62) asm volatile("cp.async.wait_group 1;" ::: "memory");
        else               asm volatile("cp.async.wait_group 0;" ::: "memory");
        __syncthreads();

        if (kt + 3 < 64) load_stage(kt + 3, (kt + 3) & 3);

        const uint32_t sOff = sb + (uint32_t)s * 8192;

        if (wid < 8) {
            // ---------------- tensor path: cols 0..79 ----------------
            #pragma unroll
            for (int ks = 0; ks < 2; ks++) {
                uint32_t a[2][4], b0[4], b1[4], b2[2];
                ldsm4(a[0], sOff + adA[0][ks]);
                ldsm4(a[1], sOff + adA[1][ks]);
                ldsm4(b0, sOff + adB4[0][ks]);
                ldsm4(b1, sOff + adB4[1][ks]);
                ldsm2(b2, sOff + adB2[ks]);
                #pragma unroll
                for (int mi = 0; mi < 2; mi++) {
                    mma_s8(accT[mi][0], a[mi], b0);
                    mma_s8(accT[mi][1], a[mi], b0 + 2);
                    mma_s8(accT[mi][2], a[mi], b1);
                    mma_s8(accT[mi][3], a[mi], b1 + 2);
                    mma_s8(accT[mi][4], a[mi], b2);
                }
            }
        } else {
            // ---------------- dp4a path: cols 80..127 ----------------
            const uint32_t bCB = sOff + bColRel;
            #pragma unroll
            for (int cgi = 0; cgi < 4; cgi++) {
                const uint32_t aBase = sOff + (uint32_t)(((cgi ^ kq) & 3) << 4);
                uint32_t a[4][4];
                #pragma unroll
                for (int ri = 0; ri < 4; ri++)
                    lds128(a[ri], aBase + aOff[ri]);
                const uint32_t be = bCB + (uint32_t)(((cgi ^ hB) & 3) << 4);
                const uint32_t bo = be ^ 0x20u;
                #pragma unroll
                for (int cj = 0; cj < 12; cj++) {
                    uint32_t bb4[4];
                    lds128(bb4, ((cj & 1) ? bo : be) + (uint32_t)cj * 256);
                    #pragma unroll
                    for (int kk = 0; kk < 4; kk++)
                        #pragma unroll
                        for (int ri = 0; ri < 4; ri++)
                            accD[ri][cj] =
                                __dp4a((int)a[ri][kk], (int)bb4[kk], accD[ri][cj]);
                }
            }
        }
    }

    // ---- fused epilogue: out = float(acc) * sx[row] * sw[col] + bias[col] ----
    if (wid < 8) {
        const int r0 = lane >> 2;
        const int cq = (lane & 3) * 2;
        #pragma unroll
        for (int mi = 0; mi < 2; mi++) {
            #pragma unroll
            for (int h = 0; h < 2; h++) {
                int row = m0 + wm * 32 + mi * 16 + r0 + 8 * h;
                float sx = g_sx[row];
                float* op = out + (size_t)row * ODIM + o0 + wn * 40 + cq;
                #pragma unroll
                for (int ni = 0; ni < 5; ni++) {
                    int co = o0 + wn * 40 + ni * 8 + cq;
                    float2 v;
                    v.x = (float)accT[mi][ni][2 * h]     * sx * __ldg(&g_sw[co])
                          + __ldg(&bias[co]);
                    v.y = (float)accT[mi][ni][2 * h + 1] * sx * __ldg(&g_sw[co + 1])
                          + __ldg(&bias[co + 1]);
                    *(float2*)(op + ni * 8) = v;
                }
            }
        }
    } else {
        const int cb = o0 + 80 + c4;
        #pragma unroll
        for (int ri = 0; ri < 4; ri++) {
            int row = m0 + wd * 32 + q + 8 * ri;
            float sx = g_sx[row];
            float* op = out + (size_t)row * ODIM + cb;
            #pragma unroll
            for (int cj = 0; cj < 12; cj++) {
                int co = cb + 4 * cj;
                op[4 * cj] = (float)accD[ri][cj] * sx * __ldg(&g_sw[co])
                             + __ldg(&bias[co]);
            }
        }
    }
}

// ---------------------------------------------------------------------------
extern "C" void kernel_launch(void* const* d_in, const int* in_sizes, int n_in,
                              void* d_out, int out_size) {
    const float* x     = (const float*)d_in[0];
    const int*   wp    = (const int*)  d_in[1];
    const float* up    = (const float*)d_in[2];
    const float* down  = (const float*)d_in[3];
    const float* scale = (const float*)d_in[4];
    const float* zp    = (const float*)d_in[5];
    const float* bias  = (const float*)d_in[6];
    float* out = (float*)d_out;

    k_quant_x<<<NTOK, 256>>>(x);
    k_corr<<<dim3(IDIM / 64, ODIM / 64), 256>>>(up, down);
    k_quant_w<<<ODIM, 256>>>(wp, scale, zp);

    static int smem_set = 0;
    if (!smem_set) {
        cudaFuncSetAttribute(k_gemm, cudaFuncAttributeMaxDynamicSharedMemorySize,
                             GEMM_SMEM);
        smem_set = 1;
    }
    k_gemm<<<dim3(ODIM / 128, NTOK / 128), NTHREADS, GEMM_SMEM>>>(bias, out);
}